// round 11
// baseline (speedup 1.0000x reference)
#include <cuda_runtime.h>

// Problem constants: B=1, Cin=64, D=16, H=64, W=64, C_OUT=64, K=3, PAD=1
#define N_VOX 65536      // 16*64*64
#define DIMD 16
#define DIMH 64
#define DIMW 64

// Contiguous scratch: q at rows [0,64), k at [64,128), v at [128,192)
__device__ float g_qkv[192 * N_VOX];

// ---------------- helpers ----------------
__device__ __forceinline__ unsigned long long ffma2(unsigned long long a,
                                                    unsigned long long b,
                                                    unsigned long long c) {
    unsigned long long d;
    asm("fma.rn.f32x2 %0, %1, %2, %3;" : "=l"(d) : "l"(a), "l"(b), "l"(c));
    return d;
}
__device__ __forceinline__ unsigned long long pack2(float lo, float hi) {
    unsigned long long r;
    asm("mov.b64 %0, {%1, %2};" : "=l"(r) : "f"(lo), "f"(hi));
    return r;
}
__device__ __forceinline__ float ex2f(float x) {
    float y; asm("ex2.approx.ftz.f32 %0, %1;" : "=f"(y) : "f"(x)); return y;
}
__device__ __forceinline__ float rcpf(float x) {
    float y; asm("rcp.approx.ftz.f32 %0, %1;" : "=f"(y) : "f"(x)); return y;
}

// ---------------- Pass 1: qkv = W · x  — register-tiled SGEMM ----------------
// C[192, 65536] = W[192,64] @ X[64, 65536].
// Block tile: 192(M) x 128(N) — full M in one block (X read once).
// Grid 512 n-tiles, 256 threads, thread tile 12(M) x 8(N) = 48 f32x2 accs.
// smem: sw[192][65] padded (48.75KB, stride-65 kills the tm-group bank
// conflict on broadcast a-loads) + sx[64][128] (32KB) ~= 81KB, 2 blocks/SM.
// Per warp-k-step: 24 FFMA2-issue cyc vs 20 smem wavefronts -> fma-bound.
__global__ __launch_bounds__(256, 2) void qkv_gemm(const float* __restrict__ x,
                                                   const float* __restrict__ wq,
                                                   const float* __restrict__ wk,
                                                   const float* __restrict__ wv) {
    extern __shared__ float smem[];
    float* sw = smem;                 // [192*65] padded
    float* sx = smem + 192 * 65;      // [64*128]

    int tid = threadIdx.x;
    int bn = blockIdx.x;              // n-tile: voxels [bn*128, +128)

    // --- load W (192 rows x 64), stride-65 padded rows ---
    {
        const float4* q4 = (const float4*)wq;
        const float4* k4 = (const float4*)wk;
        const float4* v4 = (const float4*)wv;
#pragma unroll
        for (int i = 0; i < 12; i++) {
            int idx = tid + i * 256;          // 0..3071
            int row = idx >> 4;               // 0..191
            int col = idx & 15;               // 0..15 (float4 col)
            float4 t;
            if (row < 64) t = q4[row * 16 + col];
            else if (row < 128) t = k4[(row - 64) * 16 + col];
            else t = v4[(row - 128) * 16 + col];
            float* d = sw + row * 65 + col * 4;
            d[0] = t.x; d[1] = t.y; d[2] = t.z; d[3] = t.w;
        }
    }
    // --- load X tile (64 rows x 128) ---
    {
        const float4* x4 = (const float4*)x;  // row stride 16384 f4
#pragma unroll
        for (int i = 0; i < 8; i++) {
            int idx = tid + i * 256;          // 0..2047
            int row = idx >> 5;               // 0..63 (k)
            int col = idx & 31;               // 0..31 (f4 within 128)
            ((float4*)sx)[idx] = x4[row * 16384 + bn * 32 + col];
        }
    }
    __syncthreads();

    int tm = tid >> 4;          // 0..15 -> m0 = tm*12
    int tn = tid & 15;          // 0..15 -> n0 = tn*8
    int m0 = tm * 12;
    int n0 = tn * 8;

    unsigned long long acc[12][4];
#pragma unroll
    for (int j = 0; j < 12; j++)
#pragma unroll
        for (int p = 0; p < 4; p++) acc[j][p] = 0ull;

#pragma unroll 2
    for (int k = 0; k < 64; k++) {
        ulonglong2 b01 = *(const ulonglong2*)&sx[k * 128 + n0];
        ulonglong2 b23 = *(const ulonglong2*)&sx[k * 128 + n0 + 4];
        unsigned long long bp0 = b01.x, bp1 = b01.y, bp2 = b23.x, bp3 = b23.y;
#pragma unroll
        for (int j = 0; j < 12; j++) {
            float a = sw[(m0 + j) * 65 + k];
            unsigned long long ap = pack2(a, a);
            acc[j][0] = ffma2(ap, bp0, acc[j][0]);
            acc[j][1] = ffma2(ap, bp1, acc[j][1]);
            acc[j][2] = ffma2(ap, bp2, acc[j][2]);
            acc[j][3] = ffma2(ap, bp3, acc[j][3]);
        }
    }

#pragma unroll
    for (int j = 0; j < 12; j++) {
        float* dst = g_qkv + (m0 + j) * N_VOX + bn * 128 + n0;
        *(ulonglong2*)dst = make_ulonglong2(acc[j][0], acc[j][1]);
        *(ulonglong2*)(dst + 4) = make_ulonglong2(acc[j][2], acc[j][3]);
    }
}

// ---------------- Pass 2: windowed softmax-attention (30.8us, near MUFU floor)
// Block = (tile 4x8x64, channel). Lanes consecutive in w -> conflict-free smem.
// Loop over halo h-rows: each tap loaded ONCE (90 LDS.64/thread) and consumed
// by the up-to-3 outputs that use it; outputs accumulate in den[8]/ac[8].
template <int AXIS>
__device__ __forceinline__ void attn_body(const float* __restrict__ rel, int oc,
                                          int o, float* __restrict__ out,
                                          float2* skv) {
    int tid = threadIdx.x;
    int tile = blockIdx.x;           // 0..31 : 4 d-tiles x 8 h-tiles
    int d0 = (tile >> 3) * 4;
    int h0 = (tile & 7) * 8;

    const float* kg = g_qkv + (64 + o) * N_VOX;
    const float* vg = g_qkv + (128 + o) * N_VOX;

    // 1) zero-fill (covers always-zero edge cols + OOB rows)
    float4* z = (float4*)skv;        // 6*10*66 float2 = 1980 float4
    for (int i = tid; i < 1980; i += 256) z[i] = make_float4(0.f, 0.f, 0.f, 0.f);
    __syncthreads();

    // 2) interior rows: row = zd*10+zh in [0,60), 64 coalesced lanes each
    int w = tid & 63;
    int t4 = tid >> 6;
#pragma unroll 5
    for (int pass = 0; pass < 15; pass++) {
        int row = pass * 4 + t4;                  // 0..59, warp-uniform
        int zd = (row * 205) >> 11;               // row/10 for row<62
        int zh = row - zd * 10;
        int gd = d0 - 1 + zd, gh = h0 - 1 + zh;
        if (((unsigned)gd < (unsigned)DIMD) & ((unsigned)gh < (unsigned)DIMH)) {
            int gidx = (gd * DIMH + gh) * DIMW + w;
            skv[row * 66 + 1 + w] = make_float2(kg[gidx], vg[gidx]);
        }
    }

    float b0 = rel[oc * 3 + 0];
    float b1 = rel[oc * 3 + 1];
    float b2 = rel[oc * 3 + 2];

    int dz = t4;  // 0..3
    int pbase = o * N_VOX + ((d0 + dz) * DIMH + h0) * DIMW + w;
    const float* qp = g_qkv + pbase;
    float q8[8];
#pragma unroll
    for (int i = 0; i < 8; i++) q8[i] = qp[i * DIMW] * 1.4426950408889634f;

    __syncthreads();

    const float2* kvb = skv + dz * 660 + w;  // tap: (dd*10 + zh)*66 + tw

    float den[8], ac[8];
#pragma unroll
    for (int i = 0; i < 8; i++) { den[i] = 0.f; ac[i] = 0.f; }

    // log2-domain logits: arg = q'*(k + b), q' = q*log2e; softmax ratio
    // unchanged, |arg| << 127 so no max-subtraction needed.
#pragma unroll
    for (int zh = 0; zh < 10; zh++) {
#pragma unroll
        for (int dd = 0; dd < 3; dd++) {
#pragma unroll
            for (int tw = 0; tw < 3; tw++) {
                float2 kv = kvb[(dd * 10 + zh) * 66 + tw];
                float kpb;  // tap-local bias (AXIS 0/2)
                if (AXIS == 0) kpb = kv.x + (dd == 0 ? b0 : (dd == 1 ? b1 : b2));
                if (AXIS == 2) kpb = kv.x + (tw == 0 ? b0 : (tw == 1 ? b1 : b2));
#pragma unroll
                for (int j = 0; j < 3; j++) {
                    const int i = zh - 2 + j;     // output index; hh = 2-j
                    if (i >= 0 && i < 8) {
                        float arg;
                        if (AXIS == 1) {
                            float bb = (j == 2) ? b0 : (j == 1 ? b1 : b2);
                            arg = q8[i] * (kv.x + bb);
                        } else {
                            arg = q8[i] * kpb;
                        }
                        float e = ex2f(arg);
                        den[i] += e;
                        ac[i] = fmaf(e, kv.y, ac[i]);
                    }
                }
            }
        }
    }

#pragma unroll
    for (int i = 0; i < 8; i++)
        out[pbase + i * DIMW] = ac[i] * rcpf(den[i]);
}

__global__ __launch_bounds__(256, 6) void attn_all(const float* __restrict__ rd,
                                                   const float* __restrict__ rh,
                                                   const float* __restrict__ rw,
                                                   float* __restrict__ out) {
    __shared__ float2 skv[6 * 10 * 66];  // 31680 B
    int o = blockIdx.y;  // uniform per block -> no divergence
    if (o < 21) attn_body<0>(rd, o, o, out, skv);
    else if (o < 42) attn_body<1>(rh, o - 21, o, out, skv);
    else attn_body<2>(rw, o - 42, o, out, skv);
}

// ---------------- launch ----------------
extern "C" void kernel_launch(void* const* d_in, const int* in_sizes, int n_in,
                              void* d_out, int out_size) {
    const float* x  = (const float*)d_in[0];
    const float* wq = (const float*)d_in[1];
    const float* wk = (const float*)d_in[2];
    const float* wv = (const float*)d_in[3];
    const float* rd = (const float*)d_in[4];  // 21 x 3
    const float* rh = (const float*)d_in[5];  // 21 x 3
    const float* rw = (const float*)d_in[6];  // 22 x 3
    float* out = (float*)d_out;

    const int qkv_smem = (192 * 65 + 64 * 128) * 4;  // 81,728 B
    cudaFuncSetAttribute(qkv_gemm, cudaFuncAttributeMaxDynamicSharedMemorySize,
                         qkv_smem);
    qkv_gemm<<<512, 256, qkv_smem>>>(x, wq, wk, wv);

    attn_all<<<dim3(32, 64), 256>>>(rd, rh, rw, out);
}

// round 13
// speedup vs baseline: 1.3524x; 1.3524x over previous
#include <cuda_runtime.h>

// Problem constants: B=1, Cin=64, D=16, H=64, W=64, C_OUT=64, K=3, PAD=1
#define N_VOX 65536      // 16*64*64
#define DIMD 16
#define DIMH 64
#define DIMW 64

// Contiguous scratch: q at rows [0,64), k at [64,128), v at [128,192)
__device__ float g_qkv[192 * N_VOX];

// ---------------- helpers ----------------
__device__ __forceinline__ unsigned long long ffma2(unsigned long long a,
                                                    unsigned long long b,
                                                    unsigned long long c) {
    unsigned long long d;
    asm("fma.rn.f32x2 %0, %1, %2, %3;" : "=l"(d) : "l"(a), "l"(b), "l"(c));
    return d;
}
__device__ __forceinline__ unsigned long long pack2(float lo, float hi) {
    unsigned long long r;
    asm("mov.b64 %0, {%1, %2};" : "=l"(r) : "f"(lo), "f"(hi));
    return r;
}
__device__ __forceinline__ float ex2f(float x) {
    float y; asm("ex2.approx.ftz.f32 %0, %1;" : "=f"(y) : "f"(x)); return y;
}
__device__ __forceinline__ float rcpf(float x) {
    float y; asm("rcp.approx.ftz.f32 %0, %1;" : "=f"(y) : "f"(x)); return y;
}

// ---------------- Pass 1: qkv = W · x  — register-tiled SGEMM ----------------
// C[192, 65536] = W[192,64] @ X[64, 65536].
// Block tile: 192(M) x 64(N), 192 threads, thread tile 8(M) x 8(N).
// Warp = 8 tn x 4 tm groups:
//   b-loads: LDS.128 over 8 lanes x 16B = 128B contiguous, 4-way tm multicast
//            -> 1 wavefront each (2 wf/k-step).
//   a-loads: broadcast, sw stride 65 puts the 4 tm groups on banks {0,8,16,24}
//            -> 1 wavefront each (8 wf/k-step).
// Per warp-k-step: 10 smem wf vs 32 FFMA2 = 16 SM-issue cyc -> fma-bound.
// 64 f32x2 accumulators/thread; launch_bounds(192,2) = 170-reg cap (no spills).
__global__ __launch_bounds__(192, 2) void qkv_gemm(const float* __restrict__ x,
                                                   const float* __restrict__ wq,
                                                   const float* __restrict__ wk,
                                                   const float* __restrict__ wv) {
    extern __shared__ float smem[];
    float* sw = smem;                 // [192*65] padded
    float* sx = smem + 192 * 65;      // [64*64]

    int tid = threadIdx.x;
    int bn = blockIdx.x;              // n-tile: voxels [bn*64, +64)

    // --- load W (192 rows x 64) into sw, stride-65 rows ---
    {
        const float4* q4 = (const float4*)wq;
        const float4* k4 = (const float4*)wk;
        const float4* v4 = (const float4*)wv;
#pragma unroll
        for (int i = 0; i < 16; i++) {
            int idx = tid + i * 192;          // 0..3071
            int row = idx >> 4;               // 0..191
            int col = idx & 15;               // float4 col 0..15
            float4 t;
            if (row < 64) t = q4[row * 16 + col];
            else if (row < 128) t = k4[(row - 64) * 16 + col];
            else t = v4[(row - 128) * 16 + col];
            float* d = sw + row * 65 + col * 4;
            d[0] = t.x; d[1] = t.y; d[2] = t.z; d[3] = t.w;
        }
    }
    // --- load X tile (64 rows x 64 cols) ---
    {
        const float4* x4 = (const float4*)x;  // row stride 16384 f4
#pragma unroll
        for (int i = 0; i < 6; i++) {
            int idx = tid + i * 192;          // 0..1151, need 0..1023
            if (idx < 1024) {
                int row = idx >> 4;           // k 0..63
                int col = idx & 15;           // f4 col 0..15
                ((float4*)sx)[idx] = x4[row * 16384 + bn * 16 + col];
            }
        }
    }
    __syncthreads();

    int tn = tid & 7;           // column group
    int tm = tid >> 3;          // 0..23 -> m0 = tm*8
    int m0 = tm * 8;
    int tn4 = tn * 4;

    unsigned long long acc[8][4];
#pragma unroll
    for (int j = 0; j < 8; j++)
#pragma unroll
        for (int p = 0; p < 4; p++) acc[j][p] = 0ull;

#pragma unroll 2
    for (int k = 0; k < 64; k++) {
        ulonglong2 b01 = *(const ulonglong2*)&sx[k * 64 + tn4];        // n 0..31
        ulonglong2 b23 = *(const ulonglong2*)&sx[k * 64 + 32 + tn4];   // n 32..63
#pragma unroll
        for (int j = 0; j < 8; j++) {
            float a = sw[(m0 + j) * 65 + k];
            unsigned long long ap = pack2(a, a);
            acc[j][0] = ffma2(ap, b01.x, acc[j][0]);
            acc[j][1] = ffma2(ap, b01.y, acc[j][1]);
            acc[j][2] = ffma2(ap, b23.x, acc[j][2]);
            acc[j][3] = ffma2(ap, b23.y, acc[j][3]);
        }
    }

#pragma unroll
    for (int j = 0; j < 8; j++) {
        float* dst = g_qkv + (m0 + j) * N_VOX + bn * 64;
        *(ulonglong2*)(dst + tn4) = make_ulonglong2(acc[j][0], acc[j][1]);
        *(ulonglong2*)(dst + 32 + tn4) = make_ulonglong2(acc[j][2], acc[j][3]);
    }
}

// ---------------- Pass 2: windowed softmax-attention (31us, ~115% MUFU floor)
// Block = (tile 4x8x64, channel). Lanes consecutive in w -> conflict-free smem.
// Loop over halo h-rows: each tap loaded ONCE (90 LDS.64/thread) and consumed
// by the up-to-3 outputs that use it; outputs accumulate in den[8]/ac[8].
template <int AXIS>
__device__ __forceinline__ void attn_body(const float* __restrict__ rel, int oc,
                                          int o, float* __restrict__ out,
                                          float2* skv) {
    int tid = threadIdx.x;
    int tile = blockIdx.x;           // 0..31 : 4 d-tiles x 8 h-tiles
    int d0 = (tile >> 3) * 4;
    int h0 = (tile & 7) * 8;

    const float* kg = g_qkv + (64 + o) * N_VOX;
    const float* vg = g_qkv + (128 + o) * N_VOX;

    // 1) zero-fill (covers always-zero edge cols + OOB rows)
    float4* z = (float4*)skv;        // 6*10*66 float2 = 1980 float4
    for (int i = tid; i < 1980; i += 256) z[i] = make_float4(0.f, 0.f, 0.f, 0.f);
    __syncthreads();

    // 2) interior rows: row = zd*10+zh in [0,60), 64 coalesced lanes each
    int w = tid & 63;
    int t4 = tid >> 6;
#pragma unroll 5
    for (int pass = 0; pass < 15; pass++) {
        int row = pass * 4 + t4;                  // 0..59, warp-uniform
        int zd = (row * 205) >> 11;               // row/10 for row<62
        int zh = row - zd * 10;
        int gd = d0 - 1 + zd, gh = h0 - 1 + zh;
        if (((unsigned)gd < (unsigned)DIMD) & ((unsigned)gh < (unsigned)DIMH)) {
            int gidx = (gd * DIMH + gh) * DIMW + w;
            skv[row * 66 + 1 + w] = make_float2(kg[gidx], vg[gidx]);
        }
    }

    float b0 = rel[oc * 3 + 0];
    float b1 = rel[oc * 3 + 1];
    float b2 = rel[oc * 3 + 2];

    int dz = t4;  // 0..3
    int pbase = o * N_VOX + ((d0 + dz) * DIMH + h0) * DIMW + w;
    const float* qp = g_qkv + pbase;
    float q8[8];
#pragma unroll
    for (int i = 0; i < 8; i++) q8[i] = qp[i * DIMW] * 1.4426950408889634f;

    __syncthreads();

    const float2* kvb = skv + dz * 660 + w;  // tap: (dd*10 + zh)*66 + tw

    float den[8], ac[8];
#pragma unroll
    for (int i = 0; i < 8; i++) { den[i] = 0.f; ac[i] = 0.f; }

    // log2-domain logits: arg = q'*(k + b), q' = q*log2e; softmax ratio
    // unchanged, |arg| << 127 so no max-subtraction needed.
#pragma unroll
    for (int zh = 0; zh < 10; zh++) {
#pragma unroll
        for (int dd = 0; dd < 3; dd++) {
#pragma unroll
            for (int tw = 0; tw < 3; tw++) {
                float2 kv = kvb[(dd * 10 + zh) * 66 + tw];
                float kpb;  // tap-local bias (AXIS 0/2)
                if (AXIS == 0) kpb = kv.x + (dd == 0 ? b0 : (dd == 1 ? b1 : b2));
                if (AXIS == 2) kpb = kv.x + (tw == 0 ? b0 : (tw == 1 ? b1 : b2));
#pragma unroll
                for (int j = 0; j < 3; j++) {
                    const int i = zh - 2 + j;     // output index; hh = 2-j
                    if (i >= 0 && i < 8) {
                        float arg;
                        if (AXIS == 1) {
                            float bb = (j == 2) ? b0 : (j == 1 ? b1 : b2);
                            arg = q8[i] * (kv.x + bb);
                        } else {
                            arg = q8[i] * kpb;
                        }
                        float e = ex2f(arg);
                        den[i] += e;
                        ac[i] = fmaf(e, kv.y, ac[i]);
                    }
                }
            }
        }
    }

#pragma unroll
    for (int i = 0; i < 8; i++)
        out[pbase + i * DIMW] = ac[i] * rcpf(den[i]);
}

__global__ __launch_bounds__(256, 6) void attn_all(const float* __restrict__ rd,
                                                   const float* __restrict__ rh,
                                                   const float* __restrict__ rw,
                                                   float* __restrict__ out) {
    __shared__ float2 skv[6 * 10 * 66];  // 31680 B
    int o = blockIdx.y;  // uniform per block -> no divergence
    if (o < 21) attn_body<0>(rd, o, o, out, skv);
    else if (o < 42) attn_body<1>(rh, o - 21, o, out, skv);
    else attn_body<2>(rw, o - 42, o, out, skv);
}

// ---------------- launch ----------------
extern "C" void kernel_launch(void* const* d_in, const int* in_sizes, int n_in,
                              void* d_out, int out_size) {
    const float* x  = (const float*)d_in[0];
    const float* wq = (const float*)d_in[1];
    const float* wk = (const float*)d_in[2];
    const float* wv = (const float*)d_in[3];
    const float* rd = (const float*)d_in[4];  // 21 x 3
    const float* rh = (const float*)d_in[5];  // 21 x 3
    const float* rw = (const float*)d_in[6];  // 22 x 3
    float* out = (float*)d_out;

    const int qkv_smem = (192 * 65 + 64 * 64) * 4;  // 66,304 B
    cudaFuncSetAttribute(qkv_gemm, cudaFuncAttributeMaxDynamicSharedMemorySize,
                         qkv_smem);
    qkv_gemm<<<1024, 192, qkv_smem>>>(x, wq, wk, wv);

    attn_all<<<dim3(32, 64), 256>>>(rd, rh, rw, out);
}